// round 6
// baseline (speedup 1.0000x reference)
#include <cuda_runtime.h>
#include <math.h>

#define HIDDEN  256
#define GATES   1024        // 4 * HIDDEN
#define HORIZON 24
#define BATCH   32768
#define TB      16          // batch rows per block
#define THREADS 256

// Transposed recurrent weights: WT[k*GATES + r] = W_hh[r*HIDDEN + k]
__device__ float g_WT[HIDDEN * GATES];

__global__ void transpose_whh(const float* __restrict__ W) {
    int idx = blockIdx.x * blockDim.x + threadIdx.x;
    if (idx < HIDDEN * GATES) {
        int k = idx >> 10;          // 0..255
        int r = idx & (GATES - 1);  // 0..1023
        g_WT[idx] = W[r * HIDDEN + k];
    }
}

__device__ __forceinline__ float sigmoidf_(float v) {
    return 1.0f / (1.0f + expf(-v));
}

// ---- packed f32x2 helpers (SASS FFMA2 — only reachable via explicit PTX) ----
__device__ __forceinline__ unsigned long long pack2(float lo, float hi) {
    unsigned long long r;
    asm("mov.b64 %0, {%1, %2};" : "=l"(r) : "f"(lo), "f"(hi));
    return r;
}
__device__ __forceinline__ void unpack2(unsigned long long v, float& lo, float& hi) {
    asm("mov.b64 {%0, %1}, %2;" : "=f"(lo), "=f"(hi) : "l"(v));
}
__device__ __forceinline__ unsigned long long ffma2(unsigned long long a,
                                                    unsigned long long b,
                                                    unsigned long long c) {
    unsigned long long d;
    asm("fma.rn.f32x2 %0, %1, %2, %3;" : "=l"(d) : "l"(a), "l"(b), "l"(c));
    return d;
}

__global__ void __launch_bounds__(THREADS, 2)
lstm_fused_kernel(const float* __restrict__ x,
                  const float* __restrict__ h0,
                  const float* __restrict__ c0,
                  const float* __restrict__ W_ih,
                  const float* __restrict__ b_ih,
                  const float* __restrict__ b_hh,
                  const float* __restrict__ fc_W,
                  const float* __restrict__ fc_b,
                  float* __restrict__ out)
{
    // h double buffer, b-major: hs[buf][b_local*HIDDEN + k]
    __shared__ float hs[2][TB * HIDDEN];
    __shared__ float out_s[TB];
    // Packed input-path tables, keyed by (g, pair, jt): conflict-free LDS.64
    // ws[(g*2+p)*64 + jt] = pack2(W_ih[r], W_ih[r+1]),  r = g*256 + jt*4 + 2p
    // bs[...]            = pack2(b_ih[r]+b_hh[r], b_ih[r+1]+b_hh[r+1])
    __shared__ unsigned long long ws[512];
    __shared__ unsigned long long bs[512];

    const int tid = threadIdx.x;
    const int jt  = tid & 63;   // hidden-unit tile index (0..63) -> units 4*jt..4*jt+3
    const int bt  = tid >> 6;   // batch  tile index (0..3)      -> rows  4*bt..4*bt+3
    const int j0  = jt * 4;
    const int b0  = bt * 4;                 // local batch base
    const int gb0 = blockIdx.x * TB;        // global batch base

    // ---- prologue: load h tile into shared (coalesced) ----
    for (int i = tid; i < TB * HIDDEN; i += THREADS)
        hs[0][i] = h0[(size_t)gb0 * HIDDEN + i];
    if (tid < TB) out_s[tid] = 0.0f;

    // ---- build packed W_ih / bias tables (once) ----
    for (int e = tid; e < 512; e += THREADS) {
        int g  = e >> 7;            // 0..3
        int p  = (e >> 6) & 1;      // 0..1
        int j  = e & 63;            // jt
        int r  = g * HIDDEN + j * 4 + 2 * p;
        ws[(g * 2 + p) * 64 + j] = pack2(W_ih[r], W_ih[r + 1]);
        bs[(g * 2 + p) * 64 + j] = pack2(b_ih[r] + b_hh[r],
                                         b_ih[r + 1] + b_hh[r + 1]);
    }

    // ---- per-thread persistent state ----
    float creg[4][4];               // cell state in registers across all steps
    unsigned long long xp[4];       // x value duplicated into both lanes
    #pragma unroll
    for (int i = 0; i < 4; i++) {
        float xv = x[gb0 + b0 + i];
        xp[i] = pack2(xv, xv);
        float4 cv = *reinterpret_cast<const float4*>(
            &c0[(size_t)(gb0 + b0 + i) * HIDDEN + j0]);
        creg[i][0] = cv.x; creg[i][1] = cv.y; creg[i][2] = cv.z; creg[i][3] = cv.w;
    }

    float fcw[4];
    #pragma unroll
    for (int d = 0; d < 4; d++) fcw[d] = fc_W[j0 + d];
    const float fcb = fc_b[0];

    __syncthreads();

    const ulonglong2* __restrict__ WT16 = reinterpret_cast<const ulonglong2*>(g_WT);

    int cur = 0;
    for (int t = 0; t < HORIZON; t++) {
        // packed accumulators [gate][batch][d-pair], init = constant input path
        unsigned long long acc2[4][4][2];
        #pragma unroll
        for (int g = 0; g < 4; g++)
            #pragma unroll
            for (int p = 0; p < 2; p++) {
                unsigned long long wv = ws[(g * 2 + p) * 64 + jt];
                unsigned long long bv = bs[(g * 2 + p) * 64 + jt];
                #pragma unroll
                for (int i = 0; i < 4; i++)
                    acc2[g][i][p] = ffma2(xp[i], wv, bv);
            }

        const float* __restrict__ hcur = hs[cur];

        // ---- main GEMM: acc[g][i][d] += WT[k][g*256 + j0+d] * h[b0+i][k] ----
        #pragma unroll 2
        for (int k = 0; k < HIDDEN; k += 4) {
            float ha[4][4];
            #pragma unroll
            for (int i = 0; i < 4; i++) {
                float4 hv = *reinterpret_cast<const float4*>(&hcur[(b0 + i) * HIDDEN + k]);
                ha[i][0] = hv.x; ha[i][1] = hv.y; ha[i][2] = hv.z; ha[i][3] = hv.w;
            }
            #pragma unroll
            for (int kk = 0; kk < 4; kk++) {
                // WT row (k+kk): 16B element index = (k+kk)*256 + g*64 + jt
                const ulonglong2* wr = WT16 + (size_t)(k + kk) * 256 + jt;
                unsigned long long hh[4];
                #pragma unroll
                for (int i = 0; i < 4; i++) hh[i] = pack2(ha[i][kk], ha[i][kk]);
                // gate pair 0/1 (keeps W transients at 16 regs)
                {
                    ulonglong2 w0 = wr[0];
                    ulonglong2 w1 = wr[64];
                    #pragma unroll
                    for (int i = 0; i < 4; i++) {
                        acc2[0][i][0] = ffma2(w0.x, hh[i], acc2[0][i][0]);
                        acc2[0][i][1] = ffma2(w0.y, hh[i], acc2[0][i][1]);
                        acc2[1][i][0] = ffma2(w1.x, hh[i], acc2[1][i][0]);
                        acc2[1][i][1] = ffma2(w1.y, hh[i], acc2[1][i][1]);
                    }
                }
                // gate pair 2/3
                {
                    ulonglong2 w2 = wr[128];
                    ulonglong2 w3 = wr[192];
                    #pragma unroll
                    for (int i = 0; i < 4; i++) {
                        acc2[2][i][0] = ffma2(w2.x, hh[i], acc2[2][i][0]);
                        acc2[2][i][1] = ffma2(w2.y, hh[i], acc2[2][i][1]);
                        acc2[3][i][0] = ffma2(w3.x, hh[i], acc2[3][i][0]);
                        acc2[3][i][1] = ffma2(w3.y, hh[i], acc2[3][i][1]);
                    }
                }
            }
        }

        // ---- elementwise LSTM cell + fc partial ----
        const int nxt = cur ^ 1;
        #pragma unroll
        for (int i = 0; i < 4; i++) {
            float A[4][4];  // [gate][d]
            #pragma unroll
            for (int g = 0; g < 4; g++) {
                unpack2(acc2[g][i][0], A[g][0], A[g][1]);
                unpack2(acc2[g][i][1], A[g][2], A[g][3]);
            }
            float hn[4];
            float partial = 0.0f;
            #pragma unroll
            for (int d = 0; d < 4; d++) {
                float ig = sigmoidf_(A[0][d]);
                float fg = sigmoidf_(A[1][d]);
                float gg = tanhf(A[2][d]);
                float og = sigmoidf_(A[3][d]);
                float cn = fmaf(fg, creg[i][d], ig * gg);
                float hv = og * tanhf(cn);
                creg[i][d] = cn;
                hn[d] = hv;
                partial = fmaf(hv, fcw[d], partial);
            }
            *reinterpret_cast<float4*>(&hs[nxt][(b0 + i) * HIDDEN + j0]) =
                make_float4(hn[0], hn[1], hn[2], hn[3]);
            float v = partial;
            #pragma unroll
            for (int off = 16; off > 0; off >>= 1)
                v += __shfl_xor_sync(0xffffffffu, v, off);
            if ((tid & 31) == 0)
                atomicAdd(&out_s[b0 + i], v);
        }

        __syncthreads();
        if (tid < TB) {
            out[(size_t)t * BATCH + gb0 + tid] = out_s[tid] + fcb;
            out_s[tid] = 0.0f;
        }
        __syncthreads();
        cur = nxt;
    }
}

extern "C" void kernel_launch(void* const* d_in, const int* in_sizes, int n_in,
                              void* d_out, int out_size) {
    const float* x    = (const float*)d_in[0];
    const float* h    = (const float*)d_in[1];
    const float* c    = (const float*)d_in[2];
    const float* W_ih = (const float*)d_in[3];
    const float* W_hh = (const float*)d_in[4];
    const float* b_ih = (const float*)d_in[5];
    const float* b_hh = (const float*)d_in[6];
    const float* fc_W = (const float*)d_in[7];
    const float* fc_b = (const float*)d_in[8];

    transpose_whh<<<(HIDDEN * GATES + 511) / 512, 512>>>(W_hh);
    lstm_fused_kernel<<<BATCH / TB, THREADS>>>(x, h, c, W_ih, b_ih, b_hh,
                                               fc_W, fc_b, (float*)d_out);
}

// round 9
// speedup vs baseline: 1.1738x; 1.1738x over previous
#include <cuda_runtime.h>
#include <math.h>

#define HIDDEN  256
#define GATES   1024        // 4 * HIDDEN
#define HORIZON 24
#define BATCH   32768
#define TB      16          // batch rows per block
#define THREADS 256

// Transposed recurrent weights: WT[k*GATES + r] = W_hh[r*HIDDEN + k]
__device__ float g_WT[HIDDEN * GATES];

__global__ void transpose_whh(const float* __restrict__ W) {
    int idx = blockIdx.x * blockDim.x + threadIdx.x;
    if (idx < HIDDEN * GATES) {
        int k = idx >> 10;          // 0..255
        int r = idx & (GATES - 1);  // 0..1023
        g_WT[idx] = W[r * HIDDEN + k];
    }
}

__device__ __forceinline__ float sigmoidf_(float v) {
    return 1.0f / (1.0f + expf(-v));
}

// ---- packed f32x2 helpers (SASS FFMA2 — only reachable via explicit PTX) ----
__device__ __forceinline__ unsigned long long pack2(float lo, float hi) {
    unsigned long long r;
    asm("mov.b64 %0, {%1, %2};" : "=l"(r) : "f"(lo), "f"(hi));
    return r;
}
__device__ __forceinline__ void unpack2(unsigned long long v, float& lo, float& hi) {
    asm("mov.b64 {%0, %1}, %2;" : "=f"(lo), "=f"(hi) : "l"(v));
}
__device__ __forceinline__ unsigned long long ffma2(unsigned long long a,
                                                    unsigned long long b,
                                                    unsigned long long c) {
    unsigned long long d;
    asm("fma.rn.f32x2 %0, %1, %2, %3;" : "=l"(d) : "l"(a), "l"(b), "l"(c));
    return d;
}

__global__ void __launch_bounds__(THREADS, 1)
lstm_fused_kernel(const float* __restrict__ x,
                  const float* __restrict__ h0,
                  const float* __restrict__ c0,
                  const float* __restrict__ W_ih,
                  const float* __restrict__ b_ih,
                  const float* __restrict__ b_hh,
                  const float* __restrict__ fc_W,
                  const float* __restrict__ fc_b,
                  float* __restrict__ out)
{
    // h SINGLE buffer, DUPLICATED pairs: hdup[b*HIDDEN + k] = {h, h}.
    // Safe without double-buffering: all reads of h_t finish before the
    // post-GEMM barrier; all writes of h_{t+1} happen after it.
    __shared__ unsigned long long hdup[TB * HIDDEN];      // 32 KB
    __shared__ float out_s[TB];
    // Packed input-path tables keyed by (g, pair, jt)                 8 KB
    __shared__ unsigned long long ws[512];
    __shared__ unsigned long long bs[512];

    const int tid = threadIdx.x;
    const int jt  = tid & 63;   // hidden-unit tile (0..63) -> units 4*jt..4*jt+3
    const int bt  = tid >> 6;   // batch tile (0..3)        -> rows  4*bt..4*bt+3
    const int j0  = jt * 4;
    const int b0  = bt * 4;
    const int gb0 = blockIdx.x * TB;

    // ---- prologue: load h tile into shared, duplicated ----
    for (int i = tid; i < TB * HIDDEN; i += THREADS) {
        float hv = h0[(size_t)gb0 * HIDDEN + i];
        hdup[i] = pack2(hv, hv);
    }
    if (tid < TB) out_s[tid] = 0.0f;

    // ---- packed W_ih / bias tables (once) ----
    for (int e = tid; e < 512; e += THREADS) {
        int g  = e >> 7;
        int p  = (e >> 6) & 1;
        int j  = e & 63;
        int r  = g * HIDDEN + j * 4 + 2 * p;
        ws[(g * 2 + p) * 64 + j] = pack2(W_ih[r], W_ih[r + 1]);
        bs[(g * 2 + p) * 64 + j] = pack2(b_ih[r] + b_hh[r],
                                         b_ih[r + 1] + b_hh[r + 1]);
    }

    // ---- per-thread persistent state ----
    float creg[4][4];
    unsigned long long xp[4];
    #pragma unroll
    for (int i = 0; i < 4; i++) {
        float xv = x[gb0 + b0 + i];
        xp[i] = pack2(xv, xv);
        float4 cv = *reinterpret_cast<const float4*>(
            &c0[(size_t)(gb0 + b0 + i) * HIDDEN + j0]);
        creg[i][0] = cv.x; creg[i][1] = cv.y; creg[i][2] = cv.z; creg[i][3] = cv.w;
    }

    float fcw[4];
    #pragma unroll
    for (int d = 0; d < 4; d++) fcw[d] = fc_W[j0 + d];
    const float fcb = fc_b[0];

    __syncthreads();

    const ulonglong2* __restrict__ WT16 = reinterpret_cast<const ulonglong2*>(g_WT);

    for (int t = 0; t < HORIZON; t++) {
        // packed accumulators [gate][batch][pair], init = constant input path
        unsigned long long acc2[4][4][2];
        #pragma unroll
        for (int g = 0; g < 4; g++)
            #pragma unroll
            for (int p = 0; p < 2; p++) {
                unsigned long long wv = ws[(g * 2 + p) * 64 + jt];
                unsigned long long bv = bs[(g * 2 + p) * 64 + jt];
                #pragma unroll
                for (int i = 0; i < 4; i++)
                    acc2[g][i][p] = ffma2(xp[i], wv, bv);
            }

        // ---- main GEMM: all loads of a k-quad issued up front (MLP ~20),
        //      then 128 FFMA2. unroll 2 lets next-quad loads overlap FFMAs. ----
        #pragma unroll 2
        for (int k = 0; k < HIDDEN; k += 4) {
            // h pairs for 4 rows x 4 k (broadcast LDS.128, 2 duplicated ks each)
            ulonglong2 hp[4][2];
            #pragma unroll
            for (int i = 0; i < 4; i++) {
                hp[i][0] = *reinterpret_cast<const ulonglong2*>(
                    &hdup[(b0 + i) * HIDDEN + k]);
                hp[i][1] = *reinterpret_cast<const ulonglong2*>(
                    &hdup[(b0 + i) * HIDDEN + k + 2]);
            }
            // all 16 W LDG.128 for the k-quad
            ulonglong2 w[4][4];   // [kk][gate]
            #pragma unroll
            for (int kk = 0; kk < 4; kk++) {
                const ulonglong2* wr = WT16 + (size_t)(k + kk) * 256 + jt;
                w[kk][0] = wr[0];
                w[kk][1] = wr[64];
                w[kk][2] = wr[128];
                w[kk][3] = wr[192];
            }
            // compute
            #pragma unroll
            for (int kk = 0; kk < 4; kk++) {
                #pragma unroll
                for (int i = 0; i < 4; i++) {
                    unsigned long long hh =
                        (kk < 2) ? ((kk & 1) ? hp[i][0].y : hp[i][0].x)
                                 : ((kk & 1) ? hp[i][1].y : hp[i][1].x);
                    acc2[0][i][0] = ffma2(w[kk][0].x, hh, acc2[0][i][0]);
                    acc2[0][i][1] = ffma2(w[kk][0].y, hh, acc2[0][i][1]);
                    acc2[1][i][0] = ffma2(w[kk][1].x, hh, acc2[1][i][0]);
                    acc2[1][i][1] = ffma2(w[kk][1].y, hh, acc2[1][i][1]);
                    acc2[2][i][0] = ffma2(w[kk][2].x, hh, acc2[2][i][0]);
                    acc2[2][i][1] = ffma2(w[kk][2].y, hh, acc2[2][i][1]);
                    acc2[3][i][0] = ffma2(w[kk][3].x, hh, acc2[3][i][0]);
                    acc2[3][i][1] = ffma2(w[kk][3].y, hh, acc2[3][i][1]);
                }
            }
        }

        // all reads of h_t are done before any thread overwrites hdup
        __syncthreads();

        // ---- elementwise LSTM cell + fc partial ----
        #pragma unroll
        for (int i = 0; i < 4; i++) {
            float A[4][4];  // [gate][d]
            #pragma unroll
            for (int g = 0; g < 4; g++) {
                unpack2(acc2[g][i][0], A[g][0], A[g][1]);
                unpack2(acc2[g][i][1], A[g][2], A[g][3]);
            }
            float partial = 0.0f;
            unsigned long long hn[4];
            #pragma unroll
            for (int d = 0; d < 4; d++) {
                float ig = sigmoidf_(A[0][d]);
                float fg = sigmoidf_(A[1][d]);
                float gg = tanhf(A[2][d]);
                float og = sigmoidf_(A[3][d]);
                float cn = fmaf(fg, creg[i][d], ig * gg);
                float hv = og * tanhf(cn);
                creg[i][d] = cn;
                hn[d] = pack2(hv, hv);
                partial = fmaf(hv, fcw[d], partial);
            }
            // two STS.128 of duplicated pairs
            *reinterpret_cast<ulonglong2*>(&hdup[(b0 + i) * HIDDEN + j0]) =
                make_ulonglong2(hn[0], hn[1]);
            *reinterpret_cast<ulonglong2*>(&hdup[(b0 + i) * HIDDEN + j0 + 2]) =
                make_ulonglong2(hn[2], hn[3]);
            float v = partial;
            #pragma unroll
            for (int off = 16; off > 0; off >>= 1)
                v += __shfl_xor_sync(0xffffffffu, v, off);
            if ((tid & 31) == 0)
                atomicAdd(&out_s[b0 + i], v);
        }

        __syncthreads();
        if (tid < TB) {
            out[(size_t)t * BATCH + gb0 + tid] = out_s[tid] + fcb;
            out_s[tid] = 0.0f;
        }
        __syncthreads();
    }
}

extern "C" void kernel_launch(void* const* d_in, const int* in_sizes, int n_in,
                              void* d_out, int out_size) {
    const float* x    = (const float*)d_in[0];
    const float* h    = (const float*)d_in[1];
    const float* c    = (const float*)d_in[2];
    const float* W_ih = (const float*)d_in[3];
    const float* W_hh = (const float*)d_in[4];
    const float* b_ih = (const float*)d_in[5];
    const float* b_hh = (const float*)d_in[6];
    const float* fc_W = (const float*)d_in[7];
    const float* fc_b = (const float*)d_in[8];

    transpose_whh<<<(HIDDEN * GATES + 511) / 512, 512>>>(W_hh);
    lstm_fused_kernel<<<BATCH / TB, THREADS>>>(x, h, c, W_ih, b_ih, b_hh,
                                               fc_W, fc_b, (float*)d_out);
}

// round 10
// speedup vs baseline: 1.2705x; 1.0824x over previous
#include <cuda_runtime.h>
#include <math.h>

#define HIDDEN  256
#define GATES   1024        // 4 * HIDDEN
#define HORIZON 24
#define BATCH   32768
#define TB      16          // batch rows per block
#define THREADS 256

// Transposed recurrent weights: WT[k*GATES + r] = W_hh[r*HIDDEN + k]
__device__ float g_WT[HIDDEN * GATES];

__global__ void transpose_whh(const float* __restrict__ W) {
    int idx = blockIdx.x * blockDim.x + threadIdx.x;
    if (idx < HIDDEN * GATES) {
        int k = idx >> 10;          // 0..255
        int r = idx & (GATES - 1);  // 0..1023
        g_WT[idx] = W[r * HIDDEN + k];
    }
}

__device__ __forceinline__ float sigmoidf_(float v) {
    return 1.0f / (1.0f + expf(-v));
}

// ---- packed f32x2 helpers (SASS FFMA2 — only reachable via explicit PTX) ----
__device__ __forceinline__ unsigned long long pack2(float lo, float hi) {
    unsigned long long r;
    asm("mov.b64 %0, {%1, %2};" : "=l"(r) : "f"(lo), "f"(hi));
    return r;
}
__device__ __forceinline__ void unpack2(unsigned long long v, float& lo, float& hi) {
    asm("mov.b64 {%0, %1}, %2;" : "=f"(lo), "=f"(hi) : "l"(v));
}
__device__ __forceinline__ unsigned long long ffma2(unsigned long long a,
                                                    unsigned long long b,
                                                    unsigned long long c) {
    unsigned long long d;
    asm("fma.rn.f32x2 %0, %1, %2, %3;" : "=l"(d) : "l"(a), "l"(b), "l"(c));
    return d;
}

__global__ void __launch_bounds__(THREADS, 1)
lstm_fused_kernel(const float* __restrict__ x,
                  const float* __restrict__ h0,
                  const float* __restrict__ c0,
                  const float* __restrict__ W_ih,
                  const float* __restrict__ b_ih,
                  const float* __restrict__ b_hh,
                  const float* __restrict__ fc_W,
                  const float* __restrict__ fc_b,
                  float* __restrict__ out)
{
    // h_t, plain float, b-major                                      16 KB
    __shared__ float hs[TB * HIDDEN];
    // gate-exchange buffer: ex[row_in_phase][gate][jt][pair]         16 KB
    __shared__ unsigned long long ex[4][4][64][2];
    // packed input-path tables keyed by (g, pair, jt)                 8 KB
    __shared__ unsigned long long ws[512];
    __shared__ unsigned long long bs[512];
    __shared__ float out_s[TB];

    const int tid = threadIdx.x;
    const int jt  = tid & 63;   // unit-quad index -> units 4*jt..4*jt+3
    const int g   = tid >> 6;   // GEMM: this thread's gate (0..3)
    const int bt  = g;          // epilogue: row-within-phase (0..3)
    const int j0  = jt * 4;
    const int gb0 = blockIdx.x * TB;

    // ---- prologue: h tile to shared (coalesced) ----
    for (int i = tid; i < TB * HIDDEN; i += THREADS)
        hs[i] = h0[(size_t)gb0 * HIDDEN + i];
    if (tid < TB) out_s[tid] = 0.0f;

    // ---- packed W_ih / bias tables (once) ----
    for (int e = tid; e < 512; e += THREADS) {
        int gg = e >> 7;
        int p  = (e >> 6) & 1;
        int j  = e & 63;
        int r  = gg * HIDDEN + j * 4 + 2 * p;
        ws[(gg * 2 + p) * 64 + j] = pack2(W_ih[r], W_ih[r + 1]);
        bs[(gg * 2 + p) * 64 + j] = pack2(b_ih[r] + b_hh[r],
                                          b_ih[r + 1] + b_hh[r + 1]);
    }

    // ---- per-thread persistent state ----
    // GEMM phase: all 16 rows' x, duplicated pairs
    unsigned long long xpack[TB];
    #pragma unroll
    for (int r = 0; r < TB; r++) {
        float xv = x[gb0 + r];
        xpack[r] = pack2(xv, xv);
    }
    // Epilogue phase p handles local row 4p+bt, units j0..j0+3
    float creg[4][4];
    #pragma unroll
    for (int p = 0; p < 4; p++) {
        float4 cv = *reinterpret_cast<const float4*>(
            &c0[(size_t)(gb0 + 4 * p + bt) * HIDDEN + j0]);
        creg[p][0] = cv.x; creg[p][1] = cv.y; creg[p][2] = cv.z; creg[p][3] = cv.w;
    }
    float fcw[4];
    #pragma unroll
    for (int d = 0; d < 4; d++) fcw[d] = fc_W[j0 + d];
    const float fcb = fc_b[0];

    __syncthreads();

    const ulonglong2* __restrict__ WT16 = reinterpret_cast<const ulonglong2*>(g_WT);
    const float4* __restrict__ hs4r = reinterpret_cast<const float4*>(hs);

    for (int t = 0; t < HORIZON; t++) {
        // ---- init: constant input path for this thread's gate g ----
        const unsigned long long wv0 = ws[(g * 2 + 0) * 64 + jt];
        const unsigned long long wv1 = ws[(g * 2 + 1) * 64 + jt];
        const unsigned long long bv0 = bs[(g * 2 + 0) * 64 + jt];
        const unsigned long long bv1 = bs[(g * 2 + 1) * 64 + jt];
        unsigned long long acc2[TB][2];   // [row][pair]
        #pragma unroll
        for (int r = 0; r < TB; r++) {
            acc2[r][0] = ffma2(xpack[r], wv0, bv0);
            acc2[r][1] = ffma2(xpack[r], wv1, bv1);
        }

        // ---- GEMM: thread covers gate g, units j0..j0+3, ALL 16 rows.
        //      4 LDG.128 (W) + 16 broadcast LDS.128 (h) per k-quad
        //      feed 128 FFMA2 -> W L1 traffic cut 4x vs batch-split. ----
        #pragma unroll 2
        for (int k = 0; k < HIDDEN; k += 4) {
            ulonglong2 w0 = WT16[(k + 0) * 256 + g * 64 + jt];
            ulonglong2 w1 = WT16[(k + 1) * 256 + g * 64 + jt];
            ulonglong2 w2 = WT16[(k + 2) * 256 + g * 64 + jt];
            ulonglong2 w3 = WT16[(k + 3) * 256 + g * 64 + jt];
            #pragma unroll
            for (int r = 0; r < TB; r++) {
                float4 hv = hs4r[r * 64 + (k >> 2)];   // broadcast
                unsigned long long h0p = pack2(hv.x, hv.x);
                unsigned long long h1p = pack2(hv.y, hv.y);
                unsigned long long h2p = pack2(hv.z, hv.z);
                unsigned long long h3p = pack2(hv.w, hv.w);
                acc2[r][0] = ffma2(w0.x, h0p, acc2[r][0]);
                acc2[r][1] = ffma2(w0.y, h0p, acc2[r][1]);
                acc2[r][0] = ffma2(w1.x, h1p, acc2[r][0]);
                acc2[r][1] = ffma2(w1.y, h1p, acc2[r][1]);
                acc2[r][0] = ffma2(w2.x, h2p, acc2[r][0]);
                acc2[r][1] = ffma2(w2.y, h2p, acc2[r][1]);
                acc2[r][0] = ffma2(w3.x, h3p, acc2[r][0]);
                acc2[r][1] = ffma2(w3.y, h3p, acc2[r][1]);
            }
        }

        // ---- epilogue in 4 phases of 4 rows: exchange gates via smem ----
        #pragma unroll
        for (int p = 0; p < 4; p++) {
            // writer: this thread's gate values for rows 4p..4p+3
            #pragma unroll
            for (int ri = 0; ri < 4; ri++) {
                *reinterpret_cast<ulonglong2*>(&ex[ri][g][jt][0]) =
                    make_ulonglong2(acc2[4 * p + ri][0], acc2[4 * p + ri][1]);
            }
            __syncthreads();   // also guarantees GEMM reads of hs are done (p==0)

            // reader: local row 4p+bt, unit-quad jt — gather all 4 gates
            float A[4][4];
            #pragma unroll
            for (int g2 = 0; g2 < 4; g2++) {
                ulonglong2 v = *reinterpret_cast<const ulonglong2*>(&ex[bt][g2][jt][0]);
                unpack2(v.x, A[g2][0], A[g2][1]);
                unpack2(v.y, A[g2][2], A[g2][3]);
            }
            const int row = 4 * p + bt;
            float hn[4];
            float partial = 0.0f;
            #pragma unroll
            for (int d = 0; d < 4; d++) {
                float ig = sigmoidf_(A[0][d]);
                float fg = sigmoidf_(A[1][d]);
                float gg = tanhf(A[2][d]);
                float og = sigmoidf_(A[3][d]);
                float cn = fmaf(fg, creg[p][d], ig * gg);
                float hv = og * tanhf(cn);
                creg[p][d] = cn;
                hn[d] = hv;
                partial = fmaf(hv, fcw[d], partial);
            }
            // h_{t+1} write (safe: all GEMM reads finished before first barrier)
            *reinterpret_cast<float4*>(&hs[row * HIDDEN + j0]) =
                make_float4(hn[0], hn[1], hn[2], hn[3]);
            // warp reduce fc partial (whole warp shares `row`)
            float v = partial;
            #pragma unroll
            for (int off = 16; off > 0; off >>= 1)
                v += __shfl_xor_sync(0xffffffffu, v, off);
            if ((tid & 31) == 0)
                atomicAdd(&out_s[row], v);
            __syncthreads();   // ex reusable next phase
        }

        if (tid < TB) {
            out[(size_t)t * BATCH + gb0 + tid] = out_s[tid] + fcb;
            out_s[tid] = 0.0f;
        }
        __syncthreads();
    }
}

extern "C" void kernel_launch(void* const* d_in, const int* in_sizes, int n_in,
                              void* d_out, int out_size) {
    const float* x    = (const float*)d_in[0];
    const float* h    = (const float*)d_in[1];
    const float* c    = (const float*)d_in[2];
    const float* W_ih = (const float*)d_in[3];
    const float* W_hh = (const float*)d_in[4];
    const float* b_ih = (const float*)d_in[5];
    const float* b_hh = (const float*)d_in[6];
    const float* fc_W = (const float*)d_in[7];
    const float* fc_b = (const float*)d_in[8];

    transpose_whh<<<(HIDDEN * GATES + 511) / 512, 512>>>(W_hh);
    lstm_fused_kernel<<<BATCH / TB, THREADS>>>(x, h, c, W_ih, b_ih, b_hh,
                                               fc_W, fc_b, (float*)d_out);
}

// round 13
// speedup vs baseline: 3.1386x; 2.4703x over previous
#include <cuda_runtime.h>
#include <math.h>
#include <stdint.h>

#define HIDDEN  256
#define HORIZON 24
#define BATCH   32768
#define MTILE   64
#define THREADS 256
#define NBLK    (BATCH / MTILE)      // 512 CTAs
#define HS_STRIDE 260                // 256 + 4 pad -> conflict-free A-frag LDS

// W_hh as tf32 in MMA-fragment order:
// idx = ((s*32+ks)*16+ntp)*128 + lane*4 + j
//   s: N-slice (0..3), ks: k-step of 8 (0..31), ntp: n-tile pair (0..15)
//   j: {b0,b1 of tile 2ntp, b0,b1 of tile 2ntp+1}
__device__ uint32_t g_WB[4 * 32 * 16 * 128];   // 1 MB
__device__ float    g_c[BATCH * HIDDEN];       // 32 MB cell-state scratch

__device__ __forceinline__ uint32_t f2tf32(float f) {
    uint32_t u;
    asm("cvt.rna.tf32.f32 %0, %1;" : "=r"(u) : "f"(f));
    return u;
}
__device__ __forceinline__ float sigmoidf_(float v) { return 1.0f / (1.0f + expf(-v)); }

__global__ void prep_wb(const float* __restrict__ W) {
    int idx = blockIdx.x * blockDim.x + threadIdx.x;   // 262144 total
    if (idx >= 4 * 32 * 16 * 128) return;
    int lane2 = idx & 127;
    int lane  = lane2 >> 2;
    int j     = lane2 & 3;
    int rest  = idx >> 7;
    int ntp   = rest & 15;  rest >>= 4;
    int ks    = rest & 31;
    int s     = rest >> 5;
    int nt = 2 * ntp + (j >> 1);
    int e  = j & 1;
    int n_slice = nt * 8 + (lane >> 2);     // slice col = g*64 + u_local
    int g  = n_slice >> 6;
    int ul = n_slice & 63;
    int r  = g * HIDDEN + s * 64 + ul;      // original W_hh row
    int k  = ks * 8 + (lane & 3) + e * 4;
    g_WB[idx] = f2tf32(W[r * HIDDEN + k]);
}

__device__ __forceinline__ void mma8(float* d,
                                     uint32_t a0, uint32_t a1, uint32_t a2, uint32_t a3,
                                     uint32_t b0, uint32_t b1) {
    asm("mma.sync.aligned.m16n8k8.row.col.f32.tf32.tf32.f32 "
        "{%0,%1,%2,%3}, {%4,%5,%6,%7}, {%8,%9}, {%0,%1,%2,%3};"
        : "+f"(d[0]), "+f"(d[1]), "+f"(d[2]), "+f"(d[3])
        : "r"(a0), "r"(a1), "r"(a2), "r"(a3), "r"(b0), "r"(b1));
}

// dynamic smem: uint32 hs[2][64*HS_STRIDE] | f wih[1024] | f bias[1024] | f fcw[256] | f out_s[64]
#define SMEM_WORDS (2 * 64 * HS_STRIDE + 1024 + 1024 + 256 + 64)
#define SMEM_DYN   (SMEM_WORDS * 4)

__global__ void __launch_bounds__(THREADS, 1)
lstm_mma_kernel(const float* __restrict__ x,
                const float* __restrict__ h0,
                const float* __restrict__ c0,
                const float* __restrict__ W_ih,
                const float* __restrict__ b_ih,
                const float* __restrict__ b_hh,
                const float* __restrict__ fc_W,
                const float* __restrict__ fc_b,
                float* __restrict__ out)
{
    extern __shared__ uint32_t sm[];
    uint32_t* hs     = sm;                            // 2 buffers
    float*    wih_s  = (float*)(sm + 2 * 64 * HS_STRIDE);
    float*    bias_s = wih_s + 1024;
    float*    fcw_s  = bias_s + 1024;
    float*    out_s  = fcw_s + 256;

    const int tid  = threadIdx.x;
    const int lane = tid & 31;
    const int w    = tid >> 5;
    const int mt   = w >> 1;            // m-tile (16 rows) 0..3
    const int s0   = (w & 1) * 2;       // this warp's slice base (2 slices)
    const int gid  = lane >> 2;
    const int tig  = lane & 3;
    const int r0   = mt * 16 + gid;     // local row (row r0 and r0+8)
    const int gb0  = blockIdx.x * MTILE;
    const int G0   = gb0 + r0;

    // tables
    for (int i = tid; i < 1024; i += THREADS) {
        wih_s[i]  = W_ih[i];
        bias_s[i] = b_ih[i] + b_hh[i];
    }
    if (tid < 256) fcw_s[tid] = fc_W[tid];
    if (tid < MTILE) out_s[tid] = 0.0f;
    // stage h0 -> hs[0] as tf32
    for (int i = tid; i < MTILE * HIDDEN; i += THREADS) {
        int rr = i >> 8, cc = i & 255;
        hs[rr * HS_STRIDE + cc] = f2tf32(h0[(size_t)(gb0 + rr) * HIDDEN + cc]);
    }
    __syncthreads();

    const float xr0 = x[G0];
    const float xr1 = x[G0 + 8];
    const float fcb = fc_b[0];
    const uint4* __restrict__ wb4 = reinterpret_cast<const uint4*>(g_WB);

    for (int t = 0; t < HORIZON; t++) {
        const uint32_t* hc = hs + (t & 1) * (64 * HS_STRIDE);
        uint32_t*       hn = hs + ((t + 1) & 1) * (64 * HS_STRIDE);
        const uint32_t* h0r = hc + r0 * HS_STRIDE;
        const uint32_t* h1r = hc + (r0 + 8) * HS_STRIDE;
        const float* __restrict__ csrc = (t == 0) ? c0 : g_c;

        float prt0 = 0.0f, prt1 = 0.0f;

        for (int si = 0; si < 2; si++) {
            const int sl = s0 + si;

            float acc[32][4];
            #pragma unroll
            for (int n = 0; n < 32; n++)
                #pragma unroll
                for (int q = 0; q < 4; q++) acc[n][q] = 0.0f;

            // ---- MMA: m16 x n256(slice) x k256 ----
            for (int ks = 0; ks < 32; ks++) {
                const int kb = ks * 8 + tig;
                uint32_t a0 = h0r[kb];
                uint32_t a1 = h1r[kb];
                uint32_t a2 = h0r[kb + 4];
                uint32_t a3 = h1r[kb + 4];
                const uint4* wrow = wb4 + (size_t)((sl * 32 + ks) * 16) * 32 + lane;
                #pragma unroll
                for (int ntp = 0; ntp < 16; ntp++) {
                    uint4 b = wrow[(size_t)ntp * 32];
                    mma8(acc[2 * ntp],     a0, a1, a2, a3, b.x, b.y);
                    mma8(acc[2 * ntp + 1], a0, a1, a2, a3, b.z, b.w);
                }
            }

            // ---- epilogue: this warp's rows x this slice's 64 units ----
            #pragma unroll
            for (int ub = 0; ub < 8; ub++) {
                const int U0 = sl * 64 + ub * 8 + 2 * tig;
                float2 cA = *reinterpret_cast<const float2*>(&csrc[(size_t)G0 * HIDDEN + U0]);
                float2 cB = *reinterpret_cast<const float2*>(&csrc[(size_t)(G0 + 8) * HIDDEN + U0]);
                float2 cAo, cBo;
                #pragma unroll
                for (int e = 0; e < 2; e++) {
                    const int U = U0 + e;
                    const float wi_ = wih_s[U],        bi_ = bias_s[U];
                    const float wf_ = wih_s[256 + U],  bf_ = bias_s[256 + U];
                    const float wg_ = wih_s[512 + U],  bg_ = bias_s[512 + U];
                    const float wo_ = wih_s[768 + U],  bo_ = bias_s[768 + U];
                    const float fw  = fcw_s[U];
                    // rr = 0 (row r0): C frag index e
                    {
                        float pi = acc[0 * 8 + ub][e] + fmaf(xr0, wi_, bi_);
                        float pf = acc[1 * 8 + ub][e] + fmaf(xr0, wf_, bf_);
                        float pg = acc[2 * 8 + ub][e] + fmaf(xr0, wg_, bg_);
                        float po = acc[3 * 8 + ub][e] + fmaf(xr0, wo_, bo_);
                        float cp = e ? cA.y : cA.x;
                        float cn = fmaf(sigmoidf_(pf), cp, sigmoidf_(pi) * tanhf(pg));
                        float hv = sigmoidf_(po) * tanhf(cn);
                        if (e) cAo.y = cn; else cAo.x = cn;
                        hn[r0 * HS_STRIDE + U] = f2tf32(hv);
                        prt0 = fmaf(hv, fw, prt0);
                    }
                    // rr = 1 (row r0+8): C frag index 2+e
                    {
                        float pi = acc[0 * 8 + ub][2 + e] + fmaf(xr1, wi_, bi_);
                        float pf = acc[1 * 8 + ub][2 + e] + fmaf(xr1, wf_, bf_);
                        float pg = acc[2 * 8 + ub][2 + e] + fmaf(xr1, wg_, bg_);
                        float po = acc[3 * 8 + ub][2 + e] + fmaf(xr1, wo_, bo_);
                        float cp = e ? cB.y : cB.x;
                        float cn = fmaf(sigmoidf_(pf), cp, sigmoidf_(pi) * tanhf(pg));
                        float hv = sigmoidf_(po) * tanhf(cn);
                        if (e) cBo.y = cn; else cBo.x = cn;
                        hn[(r0 + 8) * HS_STRIDE + U] = f2tf32(hv);
                        prt1 = fmaf(hv, fw, prt1);
                    }
                }
                *reinterpret_cast<float2*>(&g_c[(size_t)G0 * HIDDEN + U0]) = cAo;
                *reinterpret_cast<float2*>(&g_c[(size_t)(G0 + 8) * HIDDEN + U0]) = cBo;
            }
        }

        // fc reduce across tig lanes (units are split across the 4-lane quad)
        prt0 += __shfl_xor_sync(0xffffffffu, prt0, 1);
        prt0 += __shfl_xor_sync(0xffffffffu, prt0, 2);
        prt1 += __shfl_xor_sync(0xffffffffu, prt1, 1);
        prt1 += __shfl_xor_sync(0xffffffffu, prt1, 2);
        if (tig == 0) {
            atomicAdd(&out_s[r0], prt0);
            atomicAdd(&out_s[r0 + 8], prt1);
        }

        __syncthreads();   // h_{t+1} complete in hn; out_s sums complete
        if (tid < MTILE) {
            out[(size_t)t * BATCH + gb0 + tid] = out_s[tid] + fcb;
            out_s[tid] = 0.0f;
        }
        __syncthreads();   // out_s reset visible before next step's atomics
    }
}

extern "C" void kernel_launch(void* const* d_in, const int* in_sizes, int n_in,
                              void* d_out, int out_size) {
    const float* x    = (const float*)d_in[0];
    const float* h    = (const float*)d_in[1];
    const float* c    = (const float*)d_in[2];
    const float* W_ih = (const float*)d_in[3];
    const float* W_hh = (const float*)d_in[4];
    const float* b_ih = (const float*)d_in[5];
    const float* b_hh = (const float*)d_in[6];
    const float* fc_W = (const float*)d_in[7];
    const float* fc_b = (const float*)d_in[8];

    cudaFuncSetAttribute(lstm_mma_kernel,
                         cudaFuncAttributeMaxDynamicSharedMemorySize, SMEM_DYN);

    prep_wb<<<(4 * 32 * 16 * 128 + 255) / 256, 256>>>(W_hh);
    lstm_mma_kernel<<<NBLK, THREADS, SMEM_DYN>>>(x, h, c, W_ih, b_ih, b_hh,
                                                 fc_W, fc_b, (float*)d_out);
}

// round 14
// speedup vs baseline: 3.1422x; 1.0012x over previous
#include <cuda_runtime.h>
#include <math.h>
#include <stdint.h>

#define HIDDEN  256
#define HORIZON 24
#define BATCH   32768
#define MTILE   64
#define THREADS 256
#define NBLK    (BATCH / MTILE)      // 512 CTAs
#define HS_STRIDE 260                // 256 + 4 pad -> conflict-free A-frag LDS

// W_hh as tf32 in MMA-fragment order:
// idx = ((s*32+ks)*16+ntp)*128 + lane*4 + j
//   s: N-slice (0..3), ks: k-step of 8 (0..31), ntp: n-tile pair (0..15)
//   j: {b0,b1 of tile 2ntp, b0,b1 of tile 2ntp+1}
__device__ uint32_t g_WB[4 * 32 * 16 * 128];   // 1 MB
__device__ float    g_c[BATCH * HIDDEN];       // 32 MB cell-state scratch

__device__ __forceinline__ uint32_t f2tf32(float f) {
    uint32_t u;
    asm("cvt.rna.tf32.f32 %0, %1;" : "=r"(u) : "f"(f));
    return u;
}
__device__ __forceinline__ float sigmoidf_(float v) { return 1.0f / (1.0f + expf(-v)); }

__global__ void prep_wb(const float* __restrict__ W) {
    int idx = blockIdx.x * blockDim.x + threadIdx.x;   // 262144 total
    if (idx >= 4 * 32 * 16 * 128) return;
    int lane2 = idx & 127;
    int lane  = lane2 >> 2;
    int j     = lane2 & 3;
    int rest  = idx >> 7;
    int ntp   = rest & 15;  rest >>= 4;
    int ks    = rest & 31;
    int s     = rest >> 5;
    int nt = 2 * ntp + (j >> 1);
    int e  = j & 1;
    int n_slice = nt * 8 + (lane >> 2);     // slice col = g*64 + u_local
    int g  = n_slice >> 6;
    int ul = n_slice & 63;
    int r  = g * HIDDEN + s * 64 + ul;      // original W_hh row
    int k  = ks * 8 + (lane & 3) + e * 4;
    g_WB[idx] = f2tf32(W[r * HIDDEN + k]);
}

__device__ __forceinline__ void mma8(float* d,
                                     uint32_t a0, uint32_t a1, uint32_t a2, uint32_t a3,
                                     uint32_t b0, uint32_t b1) {
    asm("mma.sync.aligned.m16n8k8.row.col.f32.tf32.tf32.f32 "
        "{%0,%1,%2,%3}, {%4,%5,%6,%7}, {%8,%9}, {%0,%1,%2,%3};"
        : "+f"(d[0]), "+f"(d[1]), "+f"(d[2]), "+f"(d[3])
        : "r"(a0), "r"(a1), "r"(a2), "r"(a3), "r"(b0), "r"(b1));
}

// dynamic smem: uint32 hs[2][64*HS_STRIDE] | f wih[1024] | f bias[1024] | f fcw[256] | f out_s[64]
#define SMEM_WORDS (2 * 64 * HS_STRIDE + 1024 + 1024 + 256 + 64)
#define SMEM_DYN   (SMEM_WORDS * 4)

__global__ void __launch_bounds__(THREADS, 1)
lstm_mma_kernel(const float* __restrict__ x,
                const float* __restrict__ h0,
                const float* __restrict__ c0,
                const float* __restrict__ W_ih,
                const float* __restrict__ b_ih,
                const float* __restrict__ b_hh,
                const float* __restrict__ fc_W,
                const float* __restrict__ fc_b,
                float* __restrict__ out)
{
    extern __shared__ uint32_t sm[];
    uint32_t* hs     = sm;                            // 2 buffers
    float*    wih_s  = (float*)(sm + 2 * 64 * HS_STRIDE);
    float*    bias_s = wih_s + 1024;
    float*    fcw_s  = bias_s + 1024;
    float*    out_s  = fcw_s + 256;

    const int tid  = threadIdx.x;
    const int lane = tid & 31;
    const int w    = tid >> 5;
    const int mt   = w >> 1;            // m-tile (16 rows) 0..3
    const int s0   = (w & 1) * 2;       // this warp's slice base (2 slices)
    const int gid  = lane >> 2;
    const int tig  = lane & 3;
    const int r0   = mt * 16 + gid;     // local row (row r0 and r0+8)
    const int gb0  = blockIdx.x * MTILE;
    const int G0   = gb0 + r0;

    // tables
    for (int i = tid; i < 1024; i += THREADS) {
        wih_s[i]  = W_ih[i];
        bias_s[i] = b_ih[i] + b_hh[i];
    }
    if (tid < 256) fcw_s[tid] = fc_W[tid];
    if (tid < MTILE) out_s[tid] = 0.0f;
    // stage h0 -> hs[0] as tf32
    for (int i = tid; i < MTILE * HIDDEN; i += THREADS) {
        int rr = i >> 8, cc = i & 255;
        hs[rr * HS_STRIDE + cc] = f2tf32(h0[(size_t)(gb0 + rr) * HIDDEN + cc]);
    }
    __syncthreads();

    const float xr0 = x[G0];
    const float xr1 = x[G0 + 8];
    const float fcb = fc_b[0];
    const uint4* __restrict__ wb4 = reinterpret_cast<const uint4*>(g_WB);

    for (int t = 0; t < HORIZON; t++) {
        const uint32_t* hc = hs + (t & 1) * (64 * HS_STRIDE);
        uint32_t*       hn = hs + ((t + 1) & 1) * (64 * HS_STRIDE);
        const uint32_t* h0r = hc + r0 * HS_STRIDE;
        const uint32_t* h1r = hc + (r0 + 8) * HS_STRIDE;
        const float* __restrict__ csrc = (t == 0) ? c0 : g_c;

        float prt0 = 0.0f, prt1 = 0.0f;

        for (int si = 0; si < 2; si++) {
            const int sl = s0 + si;

            float acc[32][4];
            #pragma unroll
            for (int n = 0; n < 32; n++)
                #pragma unroll
                for (int q = 0; q < 4; q++) acc[n][q] = 0.0f;

            // ---- MMA: m16 x n256(slice) x k256 ----
            for (int ks = 0; ks < 32; ks++) {
                const int kb = ks * 8 + tig;
                uint32_t a0 = h0r[kb];
                uint32_t a1 = h1r[kb];
                uint32_t a2 = h0r[kb + 4];
                uint32_t a3 = h1r[kb + 4];
                const uint4* wrow = wb4 + (size_t)((sl * 32 + ks) * 16) * 32 + lane;
                #pragma unroll
                for (int ntp = 0; ntp < 16; ntp++) {
                    uint4 b = wrow[(size_t)ntp * 32];
                    mma8(acc[2 * ntp],     a0, a1, a2, a3, b.x, b.y);
                    mma8(acc[2 * ntp + 1], a0, a1, a2, a3, b.z, b.w);
                }
            }

            // ---- epilogue: this warp's rows x this slice's 64 units ----
            #pragma unroll
            for (int ub = 0; ub < 8; ub++) {
                const int U0 = sl * 64 + ub * 8 + 2 * tig;
                float2 cA = *reinterpret_cast<const float2*>(&csrc[(size_t)G0 * HIDDEN + U0]);
                float2 cB = *reinterpret_cast<const float2*>(&csrc[(size_t)(G0 + 8) * HIDDEN + U0]);
                float2 cAo, cBo;
                #pragma unroll
                for (int e = 0; e < 2; e++) {
                    const int U = U0 + e;
                    const float wi_ = wih_s[U],        bi_ = bias_s[U];
                    const float wf_ = wih_s[256 + U],  bf_ = bias_s[256 + U];
                    const float wg_ = wih_s[512 + U],  bg_ = bias_s[512 + U];
                    const float wo_ = wih_s[768 + U],  bo_ = bias_s[768 + U];
                    const float fw  = fcw_s[U];
                    // rr = 0 (row r0): C frag index e
                    {
                        float pi = acc[0 * 8 + ub][e] + fmaf(xr0, wi_, bi_);
                        float pf = acc[1 * 8 + ub][e] + fmaf(xr0, wf_, bf_);
                        float pg = acc[2 * 8 + ub][e] + fmaf(xr0, wg_, bg_);
                        float po = acc[3 * 8 + ub][e] + fmaf(xr0, wo_, bo_);
                        float cp = e ? cA.y : cA.x;
                        float cn = fmaf(sigmoidf_(pf), cp, sigmoidf_(pi) * tanhf(pg));
                        float hv = sigmoidf_(po) * tanhf(cn);
                        if (e) cAo.y = cn; else cAo.x = cn;
                        hn[r0 * HS_STRIDE + U] = f2tf32(hv);
                        prt0 = fmaf(hv, fw, prt0);
                    }
                    // rr = 1 (row r0+8): C frag index 2+e
                    {
                        float pi = acc[0 * 8 + ub][2 + e] + fmaf(xr1, wi_, bi_);
                        float pf = acc[1 * 8 + ub][2 + e] + fmaf(xr1, wf_, bf_);
                        float pg = acc[2 * 8 + ub][2 + e] + fmaf(xr1, wg_, bg_);
                        float po = acc[3 * 8 + ub][2 + e] + fmaf(xr1, wo_, bo_);
                        float cp = e ? cB.y : cB.x;
                        float cn = fmaf(sigmoidf_(pf), cp, sigmoidf_(pi) * tanhf(pg));
                        float hv = sigmoidf_(po) * tanhf(cn);
                        if (e) cBo.y = cn; else cBo.x = cn;
                        hn[(r0 + 8) * HS_STRIDE + U] = f2tf32(hv);
                        prt1 = fmaf(hv, fw, prt1);
                    }
                }
                *reinterpret_cast<float2*>(&g_c[(size_t)G0 * HIDDEN + U0]) = cAo;
                *reinterpret_cast<float2*>(&g_c[(size_t)(G0 + 8) * HIDDEN + U0]) = cBo;
            }
        }

        // fc reduce across tig lanes (units are split across the 4-lane quad)
        prt0 += __shfl_xor_sync(0xffffffffu, prt0, 1);
        prt0 += __shfl_xor_sync(0xffffffffu, prt0, 2);
        prt1 += __shfl_xor_sync(0xffffffffu, prt1, 1);
        prt1 += __shfl_xor_sync(0xffffffffu, prt1, 2);
        if (tig == 0) {
            atomicAdd(&out_s[r0], prt0);
            atomicAdd(&out_s[r0 + 8], prt1);
        }

        __syncthreads();   // h_{t+1} complete in hn; out_s sums complete
        if (tid < MTILE) {
            out[(size_t)t * BATCH + gb0 + tid] = out_s[tid] + fcb;
            out_s[tid] = 0.0f;
        }
        __syncthreads();   // out_s reset visible before next step's atomics
    }
}

extern "C" void kernel_launch(void* const* d_in, const int* in_sizes, int n_in,
                              void* d_out, int out_size) {
    const float* x    = (const float*)d_in[0];
    const float* h    = (const float*)d_in[1];
    const float* c    = (const float*)d_in[2];
    const float* W_ih = (const float*)d_in[3];
    const float* W_hh = (const float*)d_in[4];
    const float* b_ih = (const float*)d_in[5];
    const float* b_hh = (const float*)d_in[6];
    const float* fc_W = (const float*)d_in[7];
    const float* fc_b = (const float*)d_in[8];

    cudaFuncSetAttribute(lstm_mma_kernel,
                         cudaFuncAttributeMaxDynamicSharedMemorySize, SMEM_DYN);

    prep_wb<<<(4 * 32 * 16 * 128 + 255) / 256, 256>>>(W_hh);
    lstm_mma_kernel<<<NBLK, THREADS, SMEM_DYN>>>(x, h, c, W_ih, b_ih, b_hh,
                                                 fc_W, fc_b, (float*)d_out);
}

// round 15
// speedup vs baseline: 3.8089x; 1.2122x over previous
#include <cuda_runtime.h>
#include <math.h>
#include <stdint.h>

#define HIDDEN  256
#define HORIZON 24
#define BATCH   32768
#define MTILE   64
#define THREADS 256
#define NBLK    (BATCH / MTILE)      // 512 CTAs
#define HSTR    260                  // 256 + 4 pad -> conflict-free scalar LDS

// W_hh as tf32 in MMA-fragment order with 4x m-reuse tiling:
// word idx = ((((w*2+h)*32+ks)*4+np)*128) + lane*4 + jj
//   w: warp (0..7)  h: half-group (0..1)  ks: k-step (0..31)
//   np: n-tile pair (0..3)  jj: {b0,b1 of nt 2np, b0,b1 of nt 2np+1}
// column decode within (w,h): sub = nt*8 + (lane>>2) in [0,64):
//   sub<32 : gate = sub&1,     unit_lo = sub>>1
//   sub>=32: gate = 2+(sub&1), unit_lo = (sub-32)>>1
//   unit j = w*32 + h*16 + unit_lo ;  W row r = gate*256 + j ; k = ks*8+(lane&3)+4e
__device__ uint32_t g_WB[16 * 32 * 4 * 128];   // 1 MB

__device__ __forceinline__ uint32_t f2tf32(float f) {
    uint32_t u;
    asm("cvt.rna.tf32.f32 %0, %1;" : "=r"(u) : "f"(f));
    return u;
}
__device__ __forceinline__ float sigmoidf_(float v) { return 1.0f / (1.0f + expf(-v)); }

__global__ void prep_wb(const float* __restrict__ W) {
    int idx = blockIdx.x * blockDim.x + threadIdx.x;   // 262144 total
    if (idx >= 16 * 32 * 4 * 128) return;
    int jj   = idx & 3;
    int lane = (idx >> 2) & 31;
    int np   = (idx >> 7) & 3;
    int ks   = (idx >> 9) & 31;
    int wh   = idx >> 14;            // 0..15
    int w = wh >> 1, h = wh & 1;
    int nt = 2 * np + (jj >> 1);
    int e  = jj & 1;
    int gid_n = lane >> 2, tig = lane & 3;
    int sub = nt * 8 + gid_n;
    int g, jl;
    if (sub < 32) { g = sub & 1;        jl = sub >> 1; }
    else          { g = 2 + (sub & 1);  jl = (sub - 32) >> 1; }
    int j = w * 32 + h * 16 + jl;
    int r = g * HIDDEN + j;
    int k = ks * 8 + tig + 4 * e;
    g_WB[idx] = f2tf32(W[r * HIDDEN + k]);
}

__device__ __forceinline__ void mma8(float* d,
                                     uint32_t a0, uint32_t a1, uint32_t a2, uint32_t a3,
                                     uint32_t b0, uint32_t b1) {
    asm("mma.sync.aligned.m16n8k8.row.col.f32.tf32.tf32.f32 "
        "{%0,%1,%2,%3}, {%4,%5,%6,%7}, {%8,%9}, {%0,%1,%2,%3};"
        : "+f"(d[0]), "+f"(d[1]), "+f"(d[2]), "+f"(d[3])
        : "r"(a0), "r"(a1), "r"(a2), "r"(a3), "r"(b0), "r"(b1));
}

// smem words: hs[2][64*HSTR] | cs[64*HSTR] | wih[1024] | bias[1024] | fcw[256] | out[64]
#define SM_HS0   0
#define SM_HS1   (64 * HSTR)
#define SM_CS    (2 * 64 * HSTR)
#define SM_WIH   (SM_CS + 64 * HSTR)
#define SM_BIAS  (SM_WIH + 1024)
#define SM_FCW   (SM_BIAS + 1024)
#define SM_OUT   (SM_FCW + 256)
#define SMEM_DYN ((SM_OUT + 64) * 4)     // 209,152 B

__global__ void __launch_bounds__(THREADS, 1)
lstm_mma_kernel(const float* __restrict__ x,
                const float* __restrict__ h0,
                const float* __restrict__ c0,
                const float* __restrict__ W_ih,
                const float* __restrict__ b_ih,
                const float* __restrict__ b_hh,
                const float* __restrict__ fc_W,
                const float* __restrict__ fc_b,
                float* __restrict__ out)
{
    extern __shared__ uint32_t sm[];
    uint32_t* hsb    = sm;
    float*    cs     = (float*)(sm + SM_CS);
    float*    wih_s  = (float*)(sm + SM_WIH);
    float*    bias_s = (float*)(sm + SM_BIAS);
    float*    fcw_s  = (float*)(sm + SM_FCW);
    float*    out_s  = (float*)(sm + SM_OUT);

    const int tid  = threadIdx.x;
    const int lane = tid & 31;
    const int w    = tid >> 5;
    const int gid  = lane >> 2;
    const int tig  = lane & 3;
    const int gb0  = blockIdx.x * MTILE;

    // tables + state staging
    for (int i = tid; i < 1024; i += THREADS) {
        wih_s[i]  = W_ih[i];
        bias_s[i] = b_ih[i] + b_hh[i];
    }
    if (tid < 256) fcw_s[tid] = fc_W[tid];
    if (tid < MTILE) out_s[tid] = 0.0f;
    for (int i = tid; i < MTILE * HIDDEN; i += THREADS) {
        int rr = i >> 8, cc = i & 255;
        hsb[SM_HS0 + rr * HSTR + cc] = f2tf32(h0[(size_t)(gb0 + rr) * HIDDEN + cc]);
        cs[rr * HSTR + cc]           = c0[(size_t)(gb0 + rr) * HIDDEN + cc];
    }
    __syncthreads();

    float xr[4][2];
    #pragma unroll
    for (int mt = 0; mt < 4; mt++)
        #pragma unroll
        for (int rr = 0; rr < 2; rr++)
            xr[mt][rr] = x[gb0 + mt * 16 + gid + 8 * rr];
    const float fcb = fc_b[0];

    const uint4* __restrict__ wb4 = reinterpret_cast<const uint4*>(g_WB);

    for (int t = 0; t < HORIZON; t++) {
        const uint32_t* hc = hsb + ((t & 1) ? SM_HS1 : SM_HS0);
        uint32_t*       hn = hsb + ((t & 1) ? SM_HS0 : SM_HS1);

        float prt[4][2];
        #pragma unroll
        for (int mt = 0; mt < 4; mt++) { prt[mt][0] = 0.0f; prt[mt][1] = 0.0f; }

        for (int hg = 0; hg < 2; hg++) {
            float acc[4][8][4];
            #pragma unroll
            for (int mt = 0; mt < 4; mt++)
                #pragma unroll
                for (int n = 0; n < 8; n++)
                    #pragma unroll
                    for (int q = 0; q < 4; q++) acc[mt][n][q] = 0.0f;

            const uint4* wbase = wb4 + (size_t)((w * 2 + hg) * 32) * 128 + lane;

            for (int ks = 0; ks < 32; ks++) {
                const int kb = ks * 8 + tig;
                uint32_t a[4][4];
                #pragma unroll
                for (int mt = 0; mt < 4; mt++) {
                    const uint32_t* hp = hc + (mt * 16 + gid) * HSTR;
                    a[mt][0] = hp[kb];
                    a[mt][1] = hp[8 * HSTR + kb];
                    a[mt][2] = hp[kb + 4];
                    a[mt][3] = hp[8 * HSTR + kb + 4];
                }
                const uint4* wrow = wbase + (size_t)ks * 128;
                #pragma unroll
                for (int np = 0; np < 4; np++) {
                    uint4 b = wrow[np * 32];
                    #pragma unroll
                    for (int mt = 0; mt < 4; mt++) {
                        mma8(acc[mt][2 * np],
                             a[mt][0], a[mt][1], a[mt][2], a[mt][3], b.x, b.y);
                        mma8(acc[mt][2 * np + 1],
                             a[mt][0], a[mt][1], a[mt][2], a[mt][3], b.z, b.w);
                    }
                }
            }

            // ---- epilogue for this half-group: lane owns all 4 gates of
            //      units j = w*32 + hg*16 + ui*4 + tig, rows gid(+8) x 4 mt ----
            #pragma unroll
            for (int ui = 0; ui < 4; ui++) {
                const int j = w * 32 + hg * 16 + ui * 4 + tig;
                const float wi_ = wih_s[j],        bi_ = bias_s[j];
                const float wf_ = wih_s[256 + j],  bf_ = bias_s[256 + j];
                const float wg_ = wih_s[512 + j],  bg_ = bias_s[512 + j];
                const float wo_ = wih_s[768 + j],  bo_ = bias_s[768 + j];
                const float fw  = fcw_s[j];
                #pragma unroll
                for (int mt = 0; mt < 4; mt++) {
                    #pragma unroll
                    for (int rr = 0; rr < 2; rr++) {
                        const float xv = xr[mt][rr];
                        float pi = acc[mt][ui][2 * rr]         + fmaf(xv, wi_, bi_);
                        float pf = acc[mt][ui][2 * rr + 1]     + fmaf(xv, wf_, bf_);
                        float pg = acc[mt][ui + 4][2 * rr]     + fmaf(xv, wg_, bg_);
                        float po = acc[mt][ui + 4][2 * rr + 1] + fmaf(xv, wo_, bo_);
                        const int rl = mt * 16 + gid + 8 * rr;
                        float cp = cs[rl * HSTR + j];
                        float cn = fmaf(sigmoidf_(pf), cp, sigmoidf_(pi) * tanhf(pg));
                        float hv = sigmoidf_(po) * tanhf(cn);
                        cs[rl * HSTR + j] = cn;
                        hn[rl * HSTR + j] = f2tf32(hv);
                        prt[mt][rr] = fmaf(hv, fw, prt[mt][rr]);
                    }
                }
            }
        }

        // fc partials: sum over the 4 tig lanes (they hold disjoint units)
        #pragma unroll
        for (int mt = 0; mt < 4; mt++) {
            #pragma unroll
            for (int rr = 0; rr < 2; rr++) {
                float v = prt[mt][rr];
                v += __shfl_xor_sync(0xffffffffu, v, 1);
                v += __shfl_xor_sync(0xffffffffu, v, 2);
                if (tig == 0) atomicAdd(&out_s[mt * 16 + gid + 8 * rr], v);
            }
        }

        __syncthreads();   // hn, cs, out_s complete
        if (tid < MTILE) {
            out[(size_t)t * BATCH + gb0 + tid] = out_s[tid] + fcb;
            out_s[tid] = 0.0f;
        }
        __syncthreads();   // out_s reset visible before next step's atomics
    }
}

extern "C" void kernel_launch(void* const* d_in, const int* in_sizes, int n_in,
                              void* d_out, int out_size) {
    const float* x    = (const float*)d_in[0];
    const float* h    = (const float*)d_in[1];
    const float* c    = (const float*)d_in[2];
    const float* W_ih = (const float*)d_in[3];
    const float* W_hh = (const float*)d_in[4];
    const float* b_ih = (const float*)d_in[5];
    const float* b_hh = (const float*)d_in[6];
    const float* fc_W = (const float*)d_in[7];
    const float* fc_b = (const float*)d_in[8];

    cudaFuncSetAttribute(lstm_mma_kernel,
                         cudaFuncAttributeMaxDynamicSharedMemorySize, SMEM_DYN);

    prep_wb<<<(16 * 32 * 4 * 128 + 255) / 256, 256>>>(W_hh);
    lstm_mma_kernel<<<NBLK, THREADS, SMEM_DYN>>>(x, h, c, W_ih, b_ih, b_hh,
                                                 fc_W, fc_b, (float*)d_out);
}

// round 16
// speedup vs baseline: 9.1561x; 2.4039x over previous
#include <cuda_runtime.h>
#include <cuda_fp16.h>
#include <math.h>
#include <stdint.h>

#define HIDDEN  256
#define HORIZON 24
#define BATCH   32768
#define MTILE   64
#define THREADS 256
#define NBLK    (BATCH / MTILE)      // 512 CTAs
#define HSTR    132                  // h row stride in 32-bit words (128 + 4 pad)
#define CSTR    260                  // c row stride in floats (256 + 4 pad)

// W_hh as fp16 pairs in m16n8k16 fragment order with 4x m-reuse tiling:
// word idx = ((((wh)*16+ks)*4+np)*32 + lane)*4 + jj,  wh = w*2+h
//   jj = {b0,b1 of nt 2np, b0,b1 of nt 2np+1};  b0: k=16ks+2tig(+1), b1: +8
// column decode (same as tf32 version): sub = nt*8 + gid in [0,64):
//   sub<32 : gate=sub&1, jl=sub>>1 ; sub>=32: gate=2+(sub&1), jl=(sub-32)>>1
//   unit j = w*32 + h*16 + jl ; W row r = gate*256 + j
__device__ uint32_t g_WB[16 * 16 * 4 * 128];   // 512 KB

__device__ __forceinline__ float tanh_ap(float x) {
    float r;
    asm("tanh.approx.f32 %0, %1;" : "=f"(r) : "f"(x));
    return r;
}
__device__ __forceinline__ float sig_ap(float x) {
    return fmaf(tanh_ap(0.5f * x), 0.5f, 0.5f);
}

__global__ void prep_wb(const float* __restrict__ W) {
    int idx = blockIdx.x * blockDim.x + threadIdx.x;   // 131072 total
    if (idx >= 16 * 16 * 4 * 128) return;
    int jj   = idx & 3;
    int lane = (idx >> 2) & 31;
    int np   = (idx >> 7) & 3;
    int ks   = (idx >> 9) & 15;
    int wh   = idx >> 13;            // 0..15
    int w = wh >> 1, h = wh & 1;
    int nt = 2 * np + (jj >> 1);
    int e  = jj & 1;
    int gid = lane >> 2, tig = lane & 3;
    int sub = nt * 8 + gid;
    int g, jl;
    if (sub < 32) { g = sub & 1;        jl = sub >> 1; }
    else          { g = 2 + (sub & 1);  jl = (sub - 32) >> 1; }
    int j = w * 32 + h * 16 + jl;
    int r = g * HIDDEN + j;
    int k0 = ks * 16 + 2 * tig + 8 * e;
    __half2 hv = __floats2half2_rn(W[r * HIDDEN + k0], W[r * HIDDEN + k0 + 1]);
    g_WB[idx] = *reinterpret_cast<uint32_t*>(&hv);
}

__device__ __forceinline__ void mma16(float* d,
                                      uint32_t a0, uint32_t a1, uint32_t a2, uint32_t a3,
                                      uint32_t b0, uint32_t b1) {
    asm("mma.sync.aligned.m16n8k16.row.col.f32.f16.f16.f32 "
        "{%0,%1,%2,%3}, {%4,%5,%6,%7}, {%8,%9}, {%0,%1,%2,%3};"
        : "+f"(d[0]), "+f"(d[1]), "+f"(d[2]), "+f"(d[3])
        : "r"(a0), "r"(a1), "r"(a2), "r"(a3), "r"(b0), "r"(b1));
}

// smem words: hs[2][64*HSTR] | cs[64*CSTR] | wih[1024] | bias[1024] | fcw[256] | out[64]
#define SM_HS0   0
#define SM_HS1   (64 * HSTR)
#define SM_CS    (2 * 64 * HSTR)
#define SM_WIH   (SM_CS + 64 * CSTR)
#define SM_BIAS  (SM_WIH + 1024)
#define SM_FCW   (SM_BIAS + 1024)
#define SM_OUT   (SM_FCW + 256)
#define SMEM_DYN ((SM_OUT + 64) * 4)     // ~143.6 KB

__global__ void __launch_bounds__(THREADS, 1)
lstm_mma_kernel(const float* __restrict__ x,
                const float* __restrict__ h0,
                const float* __restrict__ c0,
                const float* __restrict__ W_ih,
                const float* __restrict__ b_ih,
                const float* __restrict__ b_hh,
                const float* __restrict__ fc_W,
                const float* __restrict__ fc_b,
                float* __restrict__ out)
{
    extern __shared__ uint32_t sm[];
    uint32_t* hsb    = sm;
    float*    cs     = (float*)(sm + SM_CS);
    float*    wih_s  = (float*)(sm + SM_WIH);
    float*    bias_s = (float*)(sm + SM_BIAS);
    float*    fcw_s  = (float*)(sm + SM_FCW);
    float*    out_s  = (float*)(sm + SM_OUT);

    const int tid  = threadIdx.x;
    const int lane = tid & 31;
    const int w    = tid >> 5;
    const int gid  = lane >> 2;
    const int tig  = lane & 3;
    const int gb0  = blockIdx.x * MTILE;

    // tables + state staging
    for (int i = tid; i < 1024; i += THREADS) {
        wih_s[i]  = W_ih[i];
        bias_s[i] = b_ih[i] + b_hh[i];
    }
    if (tid < 256) fcw_s[tid] = fc_W[tid];
    if (tid < MTILE) out_s[tid] = 0.0f;
    for (int i = tid; i < MTILE * 128; i += THREADS) {
        int rr = i >> 7, kw = i & 127;
        const float* hp = &h0[(size_t)(gb0 + rr) * HIDDEN + 2 * kw];
        __half2 hv = __floats2half2_rn(hp[0], hp[1]);
        hsb[SM_HS0 + rr * HSTR + kw] = *reinterpret_cast<uint32_t*>(&hv);
    }
    for (int i = tid; i < MTILE * HIDDEN; i += THREADS) {
        int rr = i >> 8, cc = i & 255;
        cs[rr * CSTR + cc] = c0[(size_t)(gb0 + rr) * HIDDEN + cc];
    }
    __syncthreads();

    float xr[4][2];
    #pragma unroll
    for (int mt = 0; mt < 4; mt++)
        #pragma unroll
        for (int rr = 0; rr < 2; rr++)
            xr[mt][rr] = x[gb0 + mt * 16 + gid + 8 * rr];
    const float fcb = fc_b[0];

    const uint4* __restrict__ wb4 = reinterpret_cast<const uint4*>(g_WB);

    for (int t = 0; t < HORIZON; t++) {
        const uint32_t* hc = hsb + ((t & 1) ? SM_HS1 : SM_HS0);
        uint32_t*       hn = hsb + ((t & 1) ? SM_HS0 : SM_HS1);
        __half*         hnh = (__half*)hn;

        float prt[4][2];
        #pragma unroll
        for (int mt = 0; mt < 4; mt++) { prt[mt][0] = 0.0f; prt[mt][1] = 0.0f; }

        for (int hg = 0; hg < 2; hg++) {
            float acc[4][8][4];
            #pragma unroll
            for (int mt = 0; mt < 4; mt++)
                #pragma unroll
                for (int n = 0; n < 8; n++)
                    #pragma unroll
                    for (int q = 0; q < 4; q++) acc[mt][n][q] = 0.0f;

            const uint4* wbase = wb4 + (size_t)((w * 2 + hg) * 16) * 128 + lane;

            #pragma unroll 4
            for (int ks = 0; ks < 16; ks++) {
                const int kb = ks * 8 + tig;
                uint32_t a[4][4];
                #pragma unroll
                for (int mt = 0; mt < 4; mt++) {
                    const uint32_t* hp = hc + (mt * 16 + gid) * HSTR;
                    a[mt][0] = hp[kb];
                    a[mt][1] = hp[8 * HSTR + kb];
                    a[mt][2] = hp[kb + 4];
                    a[mt][3] = hp[8 * HSTR + kb + 4];
                }
                const uint4* wrow = wbase + (size_t)ks * 128;
                #pragma unroll
                for (int np = 0; np < 4; np++) {
                    uint4 b = wrow[np * 32];
                    #pragma unroll
                    for (int mt = 0; mt < 4; mt++) {
                        mma16(acc[mt][2 * np],
                              a[mt][0], a[mt][1], a[mt][2], a[mt][3], b.x, b.y);
                        mma16(acc[mt][2 * np + 1],
                              a[mt][0], a[mt][1], a[mt][2], a[mt][3], b.z, b.w);
                    }
                }
            }

            // ---- epilogue: lane owns all 4 gates of units
            //      j = w*32 + hg*16 + ui*4 + tig ; rows (mt*16+gid+8rr) ----
            #pragma unroll
            for (int ui = 0; ui < 4; ui++) {
                const int j = w * 32 + hg * 16 + ui * 4 + tig;
                const float wi_ = wih_s[j],        bi_ = bias_s[j];
                const float wf_ = wih_s[256 + j],  bf_ = bias_s[256 + j];
                const float wg_ = wih_s[512 + j],  bg_ = bias_s[512 + j];
                const float wo_ = wih_s[768 + j],  bo_ = bias_s[768 + j];
                const float fw  = fcw_s[j];
                #pragma unroll
                for (int mt = 0; mt < 4; mt++) {
                    #pragma unroll
                    for (int rr = 0; rr < 2; rr++) {
                        const float xv = xr[mt][rr];
                        float pi = acc[mt][ui][2 * rr]         + fmaf(xv, wi_, bi_);
                        float pf = acc[mt][ui][2 * rr + 1]     + fmaf(xv, wf_, bf_);
                        float pg = acc[mt][ui + 4][2 * rr]     + fmaf(xv, wg_, bg_);
                        float po = acc[mt][ui + 4][2 * rr + 1] + fmaf(xv, wo_, bo_);
                        const int rl = mt * 16 + gid + 8 * rr;
                        float cp = cs[rl * CSTR + j];
                        float cn = fmaf(sig_ap(pf), cp, sig_ap(pi) * tanh_ap(pg));
                        float hv = sig_ap(po) * tanh_ap(cn);
                        cs[rl * CSTR + j] = cn;
                        hnh[rl * (HSTR * 2) + j] = __float2half_rn(hv);
                        prt[mt][rr] = fmaf(hv, fw, prt[mt][rr]);
                    }
                }
            }
        }

        // fc partials: sum over the 4 tig lanes (disjoint units)
        #pragma unroll
        for (int mt = 0; mt < 4; mt++) {
            #pragma unroll
            for (int rr = 0; rr < 2; rr++) {
                float v = prt[mt][rr];
                v += __shfl_xor_sync(0xffffffffu, v, 1);
                v += __shfl_xor_sync(0xffffffffu, v, 2);
                if (tig == 0) atomicAdd(&out_s[mt * 16 + gid + 8 * rr], v);
            }
        }

        __syncthreads();   // hn, cs, out_s complete
        if (tid < MTILE) {
            out[(size_t)t * BATCH + gb0 + tid] = out_s[tid] + fcb;
            out_s[tid] = 0.0f;
        }
        __syncthreads();   // out_s reset visible before next step's atomics
    }
}

extern "C" void kernel_launch(void* const* d_in, const int* in_sizes, int n_in,
                              void* d_out, int out_size) {
    const float* x    = (const float*)d_in[0];
    const float* h    = (const float*)d_in[1];
    const float* c    = (const float*)d_in[2];
    const float* W_ih = (const float*)d_in[3];
    const float* W_hh = (const float*)d_in[4];
    const float* b_ih = (const float*)d_in[5];
    const float* b_hh = (const float*)d_in[6];
    const float* fc_W = (const float*)d_in[7];
    const float* fc_b = (const float*)d_in[8];

    cudaFuncSetAttribute(lstm_mma_kernel,
                         cudaFuncAttributeMaxDynamicSharedMemorySize, SMEM_DYN);

    prep_wb<<<(16 * 16 * 4 * 128 + 255) / 256, 256>>>(W_hh);
    lstm_mma_kernel<<<NBLK, THREADS, SMEM_DYN>>>(x, h, c, W_ih, b_ih, b_hh,
                                                 fc_W, fc_b, (float*)d_out);
}